// round 15
// baseline (speedup 1.0000x reference)
#include <cuda_runtime.h>
#include <math.h>

// Problem constants (fixed by the reference: B=4, F=2048, D=1024, H=2048, E=8, K=2)
#define Dd 1024
#define Hh 2048
#define Ee 8
#define Tt 8192            // B*F tokens
#define Aa (Tt*2)          // total assignments (top-k = 2)

// ---------------- scratch (static __device__ allocations; no cudaMalloc) ----------------
__device__ __align__(16) float g_h[(size_t)Tt * Dd];        // router hidden  (32 MB)
__device__ __align__(16) float g_eh[(size_t)Aa * Hh];       // expert hidden  (128 MB)
__device__ __align__(16) float g_contrib[(size_t)Aa * Dd];  // weighted expert outputs (64 MB)
__device__ float g_w[Aa];      // per-assignment softmax weight, indexed by token*2+k
__device__ int   g_idx[Aa];    // per-assignment expert id,    indexed by token*2+k
__device__ int   g_list[Aa];   // packed (token*2+k), grouped contiguously per expert
__device__ int   g_cnt[Ee];
__device__ int   g_off[Ee];
__device__ int   g_cur[Ee];

__device__ __forceinline__ float silu_f(float c) { return c / (1.0f + expf(-c)); }

// ---------------- shared SGEMM mainloop: 128x128 tile, BK=8, 256 threads, 8x8/thread ----
// aPtr: this thread's A row pointer (row fixed per thread) offset by aCol
// bPtr: W + bRow*N + colBase + bCol
__device__ __forceinline__ void gemm_main(const float* __restrict__ aPtr,
                                          const float* __restrict__ bPtr,
                                          int N, int Kd,
                                          float acc[8][8],
                                          float As[8][132], float Bs[8][128],
                                          int tid)
{
    const int aRow = tid >> 1;
    const int aCol = (tid & 1) * 4;
    const int bRow = tid >> 5;
    const int bCol = (tid & 31) * 4;
    const int tx = tid & 15, ty = tid >> 4;

    float4 na = *(const float4*)(aPtr);
    float4 nb = *(const float4*)(bPtr);

    for (int k0 = 0; k0 < Kd; k0 += 8) {
        // stage into shared (A transposed, padded stride 132 -> conflict-free)
        As[aCol + 0][aRow] = na.x;
        As[aCol + 1][aRow] = na.y;
        As[aCol + 2][aRow] = na.z;
        As[aCol + 3][aRow] = na.w;
        *(float4*)&Bs[bRow][bCol] = nb;
        __syncthreads();

        // prefetch next k-tile (overlaps with compute)
        if (k0 + 8 < Kd) {
            na = *(const float4*)(aPtr + k0 + 8);
            nb = *(const float4*)(bPtr + (size_t)(k0 + 8) * N);
        }

        #pragma unroll
        for (int kk = 0; kk < 8; kk++) {
            float4 a0 = *(const float4*)&As[kk][ty * 8];
            float4 a1 = *(const float4*)&As[kk][ty * 8 + 4];
            float4 b0 = *(const float4*)&Bs[kk][tx * 8];
            float4 b1 = *(const float4*)&Bs[kk][tx * 8 + 4];
            float ar[8] = {a0.x, a0.y, a0.z, a0.w, a1.x, a1.y, a1.z, a1.w};
            float br[8] = {b0.x, b0.y, b0.z, b0.w, b1.x, b1.y, b1.z, b1.w};
            #pragma unroll
            for (int i = 0; i < 8; i++)
                #pragma unroll
                for (int j = 0; j < 8; j++)
                    acc[i][j] += ar[i] * br[j];
        }
        __syncthreads();
    }
}

// ---------------- K1: router GEMM1  h = silu(x @ rw1 + rb1),  [T,1024]x[1024,1024] -----
__global__ void __launch_bounds__(256) k_gemm_router(const float* __restrict__ X,
                                                     const float* __restrict__ W,
                                                     const float* __restrict__ b)
{
    __shared__ float As[8][132];
    __shared__ float Bs[8][128];
    const int tid = threadIdx.x;
    const int rowBase = blockIdx.y * 128;
    const int colBase = blockIdx.x * 128;

    const int aRow = tid >> 1, aCol = (tid & 1) * 4;
    const int bRow = tid >> 5, bCol = (tid & 31) * 4;
    const float* aPtr = X + (size_t)(rowBase + aRow) * Dd + aCol;
    const float* bPtr = W + (size_t)bRow * Dd + colBase + bCol;

    float acc[8][8];
    #pragma unroll
    for (int i = 0; i < 8; i++)
        #pragma unroll
        for (int j = 0; j < 8; j++) acc[i][j] = 0.0f;

    gemm_main(aPtr, bPtr, Dd, Dd, acc, As, Bs, tid);

    const int tx = tid & 15, ty = tid >> 4;
    #pragma unroll
    for (int i = 0; i < 8; i++) {
        const int r = rowBase + ty * 8 + i;
        float* o = g_h + (size_t)r * Dd + colBase + tx * 8;
        #pragma unroll
        for (int j = 0; j < 8; j++) {
            float c = acc[i][j] + b[colBase + tx * 8 + j];
            o[j] = silu_f(c);
        }
    }
}

// ---------------- K2: router logits + top-2 + softmax + expert counts ------------------
__global__ void k_router2(const float* __restrict__ rw2, const float* __restrict__ rb2, int T)
{
    const int gw = (blockIdx.x * blockDim.x + threadIdx.x) >> 5;
    const int lane = threadIdx.x & 31;
    if (gw >= T) return;

    const float* hrow = g_h + (size_t)gw * Dd;
    float acc[8] = {0.f, 0.f, 0.f, 0.f, 0.f, 0.f, 0.f, 0.f};
    for (int i = lane; i < Dd; i += 32) {
        const float hv = hrow[i];
        const float4 wa = *(const float4*)(rw2 + (size_t)i * 8);
        const float4 wb = *(const float4*)(rw2 + (size_t)i * 8 + 4);
        acc[0] += hv * wa.x; acc[1] += hv * wa.y; acc[2] += hv * wa.z; acc[3] += hv * wa.w;
        acc[4] += hv * wb.x; acc[5] += hv * wb.y; acc[6] += hv * wb.z; acc[7] += hv * wb.w;
    }
    #pragma unroll
    for (int e = 0; e < 8; e++)
        #pragma unroll
        for (int s = 16; s > 0; s >>= 1)
            acc[e] += __shfl_xor_sync(0xffffffffu, acc[e], s);

    if (lane == 0) {
        float lg[8];
        #pragma unroll
        for (int e = 0; e < 8; e++) lg[e] = acc[e] + rb2[e];
        // top-2 (ties -> lowest index, matching lax.top_k)
        int i1 = 0;
        #pragma unroll
        for (int e = 1; e < 8; e++) if (lg[e] > lg[i1]) i1 = e;
        int i2 = -1;
        #pragma unroll
        for (int e = 0; e < 8; e++)
            if (e != i1 && (i2 < 0 || lg[e] > lg[i2])) i2 = e;
        const float d = expf(lg[i2] - lg[i1]);     // <= 1
        const float w1 = 1.0f / (1.0f + d);
        const float w2 = d / (1.0f + d);
        g_idx[gw * 2 + 0] = i1; g_idx[gw * 2 + 1] = i2;
        g_w[gw * 2 + 0] = w1;  g_w[gw * 2 + 1] = w2;
        atomicAdd(&g_cnt[i1], 1);
        atomicAdd(&g_cnt[i2], 1);
    }
}

// ---------------- small helpers --------------------------------------------------------
__global__ void k_zero_cnt()
{
    const int i = threadIdx.x;
    if (i < Ee) { g_cnt[i] = 0; g_cur[i] = 0; }
}

__global__ void k_scan()
{
    if (threadIdx.x == 0) {
        int s = 0;
        for (int e = 0; e < Ee; e++) { g_off[e] = s; s += g_cnt[e]; }
    }
}

__global__ void k_place(int T)
{
    const int t = blockIdx.x * blockDim.x + threadIdx.x;
    if (t >= T) return;
    #pragma unroll
    for (int k = 0; k < 2; k++) {
        const int e = g_idx[t * 2 + k];
        const int p = atomicAdd(&g_cur[e], 1);
        g_list[g_off[e] + p] = t * 2 + k;
    }
}

// ---------------- K3: expert GEMM1  eh = silu(gather(x) @ ew1[e] + eb1[e]) -------------
__global__ void __launch_bounds__(256) k_gemm_exp1(const float* __restrict__ X,
                                                   const float* __restrict__ EW1,
                                                   const float* __restrict__ EB1)
{
    const int e = blockIdx.z;
    const int cnt = g_cnt[e];
    const int rowBase = blockIdx.x * 128;
    if (rowBase >= cnt) return;
    const int off = g_off[e];

    __shared__ float As[8][132];
    __shared__ float Bs[8][128];
    const int tid = threadIdx.x;
    const int colBase = blockIdx.y * 128;

    const int aRow = tid >> 1, aCol = (tid & 1) * 4;
    const int bRow = tid >> 5, bCol = (tid & 31) * 4;
    const int gRow = rowBase + aRow;
    const int lr = (gRow < cnt) ? gRow : (cnt - 1);
    const int packed = g_list[off + lr];
    const float* aPtr = X + (size_t)(packed >> 1) * Dd + aCol;
    const float* bPtr = EW1 + (size_t)e * Dd * Hh + (size_t)bRow * Hh + colBase + bCol;

    float acc[8][8];
    #pragma unroll
    for (int i = 0; i < 8; i++)
        #pragma unroll
        for (int j = 0; j < 8; j++) acc[i][j] = 0.0f;

    gemm_main(aPtr, bPtr, Hh, Dd, acc, As, Bs, tid);

    const int tx = tid & 15, ty = tid >> 4;
    const float* bias = EB1 + (size_t)e * Hh + colBase + tx * 8;
    #pragma unroll
    for (int i = 0; i < 8; i++) {
        const int r = rowBase + ty * 8 + i;
        if (r >= cnt) break;
        float* o = g_eh + (size_t)(off + r) * Hh + colBase + tx * 8;
        #pragma unroll
        for (int j = 0; j < 8; j++) {
            float c = acc[i][j] + bias[j];
            o[j] = silu_f(c);
        }
    }
}

// ---------------- K4: expert GEMM2  contrib = w * (eh @ ew2[e] + eb2[e]) ---------------
__global__ void __launch_bounds__(256) k_gemm_exp2(const float* __restrict__ EW2,
                                                   const float* __restrict__ EB2)
{
    const int e = blockIdx.z;
    const int cnt = g_cnt[e];
    const int rowBase = blockIdx.x * 128;
    if (rowBase >= cnt) return;
    const int off = g_off[e];

    __shared__ float As[8][132];
    __shared__ float Bs[8][128];
    const int tid = threadIdx.x;
    const int colBase = blockIdx.y * 128;

    const int aRow = tid >> 1, aCol = (tid & 1) * 4;
    const int bRow = tid >> 5, bCol = (tid & 31) * 4;
    const int gRow = rowBase + aRow;
    const int lr = (gRow < cnt) ? gRow : (cnt - 1);
    const float* aPtr = g_eh + (size_t)(off + lr) * Hh + aCol;
    const float* bPtr = EW2 + (size_t)e * Hh * Dd + (size_t)bRow * Dd + colBase + bCol;

    float acc[8][8];
    #pragma unroll
    for (int i = 0; i < 8; i++)
        #pragma unroll
        for (int j = 0; j < 8; j++) acc[i][j] = 0.0f;

    gemm_main(aPtr, bPtr, Dd, Hh, acc, As, Bs, tid);

    const int tx = tid & 15, ty = tid >> 4;
    const float* bias = EB2 + (size_t)e * Dd + colBase + tx * 8;
    #pragma unroll
    for (int i = 0; i < 8; i++) {
        const int r = rowBase + ty * 8 + i;
        if (r >= cnt) break;
        const int packed = g_list[off + r];
        const float wt = g_w[packed];
        float* o = g_contrib + (size_t)packed * Dd + colBase + tx * 8;
        #pragma unroll
        for (int j = 0; j < 8; j++)
            o[j] = wt * (acc[i][j] + bias[j]);
    }
}

// ---------------- K5: combine  out = x + contrib[2t] + contrib[2t+1] -------------------
__global__ void k_combine(const float* __restrict__ X, float* __restrict__ out, int T)
{
    const size_t i = ((size_t)blockIdx.x * blockDim.x + threadIdx.x) * 4;
    if (i >= (size_t)T * Dd) return;
    const size_t t = i / Dd;
    const size_t d = i % Dd;
    const float4 xv = *(const float4*)(X + i);
    const float4 c0 = *(const float4*)(g_contrib + (2 * t) * Dd + d);
    const float4 c1 = *(const float4*)(g_contrib + (2 * t + 1) * Dd + d);
    float4 o;
    o.x = xv.x + c0.x + c1.x;
    o.y = xv.y + c0.y + c1.y;
    o.z = xv.z + c0.z + c1.z;
    o.w = xv.w + c0.w + c1.w;
    *(float4*)(out + i) = o;
}

// ---------------- launch ----------------------------------------------------------------
extern "C" void kernel_launch(void* const* d_in, const int* in_sizes, int n_in,
                              void* d_out, int out_size)
{
    const float* x   = (const float*)d_in[0];
    const float* rw1 = (const float*)d_in[1];
    const float* rb1 = (const float*)d_in[2];
    const float* rw2 = (const float*)d_in[3];
    const float* rb2 = (const float*)d_in[4];
    const float* ew1 = (const float*)d_in[5];
    const float* eb1 = (const float*)d_in[6];
    const float* ew2 = (const float*)d_in[7];
    const float* eb2 = (const float*)d_in[8];
    float* out = (float*)d_out;

    const int T = in_sizes[0] / Dd;   // 8192 tokens

    k_zero_cnt<<<1, 32>>>();

    dim3 gR(Dd / 128, T / 128);                         // router GEMM1: 8 x 64
    k_gemm_router<<<gR, 256>>>(x, rw1, rb1);

    k_router2<<<(T * 32 + 255) / 256, 256>>>(rw2, rb2, T);
    k_scan<<<1, 1>>>();
    k_place<<<(T + 255) / 256, 256>>>(T);

    dim3 g1((2 * T + 127) / 128, Hh / 128, Ee);         // expert GEMM1
    k_gemm_exp1<<<g1, 256>>>(x, ew1, eb1);

    dim3 g2((2 * T + 127) / 128, Dd / 128, Ee);         // expert GEMM2
    k_gemm_exp2<<<g2, 256>>>(ew2, eb2);

    k_combine<<<(T * Dd / 4 + 255) / 256, 256>>>(x, out, T);
}

// round 16
// speedup vs baseline: 1.0020x; 1.0020x over previous
#include <cuda_runtime.h>
#include <math.h>

// Problem constants (fixed by the reference: B=4, F=2048, D=1024, H=2048, E=8, K=2)
#define Dd 1024
#define Hh 2048
#define Ee 8
#define Tt 8192            // B*F tokens
#define Aa (Tt*2)          // total assignments (top-k = 2)

// ---------------- scratch (static __device__ allocations; no cudaMalloc) ----------------
__device__ __align__(16) float g_h[(size_t)Tt * Dd];        // router hidden  (32 MB)
__device__ __align__(16) float g_eh[(size_t)Aa * Hh];       // expert hidden  (128 MB)
__device__ __align__(16) float g_contrib[(size_t)Aa * Dd];  // weighted expert outputs (64 MB)
__device__ float g_w[Aa];      // per-assignment softmax weight, indexed by token*2+k
__device__ int   g_idx[Aa];    // per-assignment expert id,    indexed by token*2+k
__device__ int   g_list[Aa];   // packed (token*2+k), grouped contiguously per expert
__device__ int   g_cnt[Ee];
__device__ int   g_off[Ee];
__device__ int   g_cur[Ee];

__device__ __forceinline__ float silu_f(float c) { return c / (1.0f + expf(-c)); }

// ---------------- shared SGEMM mainloop: 128x128 tile, BK=8, 256 threads, 8x8/thread ----
// aPtr: this thread's A row pointer (row fixed per thread) offset by aCol
// bPtr: W + bRow*N + colBase + bCol
__device__ __forceinline__ void gemm_main(const float* __restrict__ aPtr,
                                          const float* __restrict__ bPtr,
                                          int N, int Kd,
                                          float acc[8][8],
                                          float As[8][132], float Bs[8][128],
                                          int tid)
{
    const int aRow = tid >> 1;
    const int aCol = (tid & 1) * 4;
    const int bRow = tid >> 5;
    const int bCol = (tid & 31) * 4;
    const int tx = tid & 15, ty = tid >> 4;

    float4 na = *(const float4*)(aPtr);
    float4 nb = *(const float4*)(bPtr);

    for (int k0 = 0; k0 < Kd; k0 += 8) {
        // stage into shared (A transposed, padded stride 132 -> conflict-free)
        As[aCol + 0][aRow] = na.x;
        As[aCol + 1][aRow] = na.y;
        As[aCol + 2][aRow] = na.z;
        As[aCol + 3][aRow] = na.w;
        *(float4*)&Bs[bRow][bCol] = nb;
        __syncthreads();

        // prefetch next k-tile (overlaps with compute)
        if (k0 + 8 < Kd) {
            na = *(const float4*)(aPtr + k0 + 8);
            nb = *(const float4*)(bPtr + (size_t)(k0 + 8) * N);
        }

        #pragma unroll
        for (int kk = 0; kk < 8; kk++) {
            float4 a0 = *(const float4*)&As[kk][ty * 8];
            float4 a1 = *(const float4*)&As[kk][ty * 8 + 4];
            float4 b0 = *(const float4*)&Bs[kk][tx * 8];
            float4 b1 = *(const float4*)&Bs[kk][tx * 8 + 4];
            float ar[8] = {a0.x, a0.y, a0.z, a0.w, a1.x, a1.y, a1.z, a1.w};
            float br[8] = {b0.x, b0.y, b0.z, b0.w, b1.x, b1.y, b1.z, b1.w};
            #pragma unroll
            for (int i = 0; i < 8; i++)
                #pragma unroll
                for (int j = 0; j < 8; j++)
                    acc[i][j] += ar[i] * br[j];
        }
        __syncthreads();
    }
}

// ---------------- K1: router GEMM1  h = silu(x @ rw1 + rb1),  [T,1024]x[1024,1024] -----
__global__ void __launch_bounds__(256) k_gemm_router(const float* __restrict__ X,
                                                     const float* __restrict__ W,
                                                     const float* __restrict__ b)
{
    __shared__ float As[8][132];
    __shared__ float Bs[8][128];
    const int tid = threadIdx.x;
    const int rowBase = blockIdx.y * 128;
    const int colBase = blockIdx.x * 128;

    const int aRow = tid >> 1, aCol = (tid & 1) * 4;
    const int bRow = tid >> 5, bCol = (tid & 31) * 4;
    const float* aPtr = X + (size_t)(rowBase + aRow) * Dd + aCol;
    const float* bPtr = W + (size_t)bRow * Dd + colBase + bCol;

    float acc[8][8];
    #pragma unroll
    for (int i = 0; i < 8; i++)
        #pragma unroll
        for (int j = 0; j < 8; j++) acc[i][j] = 0.0f;

    gemm_main(aPtr, bPtr, Dd, Dd, acc, As, Bs, tid);

    const int tx = tid & 15, ty = tid >> 4;
    #pragma unroll
    for (int i = 0; i < 8; i++) {
        const int r = rowBase + ty * 8 + i;
        float* o = g_h + (size_t)r * Dd + colBase + tx * 8;
        #pragma unroll
        for (int j = 0; j < 8; j++) {
            float c = acc[i][j] + b[colBase + tx * 8 + j];
            o[j] = silu_f(c);
        }
    }
}

// ---------------- K2: router logits + top-2 + softmax + expert counts ------------------
__global__ void k_router2(const float* __restrict__ rw2, const float* __restrict__ rb2, int T)
{
    const int gw = (blockIdx.x * blockDim.x + threadIdx.x) >> 5;
    const int lane = threadIdx.x & 31;
    if (gw >= T) return;

    const float* hrow = g_h + (size_t)gw * Dd;
    float acc[8] = {0.f, 0.f, 0.f, 0.f, 0.f, 0.f, 0.f, 0.f};
    for (int i = lane; i < Dd; i += 32) {
        const float hv = hrow[i];
        const float4 wa = *(const float4*)(rw2 + (size_t)i * 8);
        const float4 wb = *(const float4*)(rw2 + (size_t)i * 8 + 4);
        acc[0] += hv * wa.x; acc[1] += hv * wa.y; acc[2] += hv * wa.z; acc[3] += hv * wa.w;
        acc[4] += hv * wb.x; acc[5] += hv * wb.y; acc[6] += hv * wb.z; acc[7] += hv * wb.w;
    }
    #pragma unroll
    for (int e = 0; e < 8; e++)
        #pragma unroll
        for (int s = 16; s > 0; s >>= 1)
            acc[e] += __shfl_xor_sync(0xffffffffu, acc[e], s);

    if (lane == 0) {
        float lg[8];
        #pragma unroll
        for (int e = 0; e < 8; e++) lg[e] = acc[e] + rb2[e];
        // top-2 (ties -> lowest index, matching lax.top_k)
        int i1 = 0;
        #pragma unroll
        for (int e = 1; e < 8; e++) if (lg[e] > lg[i1]) i1 = e;
        int i2 = -1;
        #pragma unroll
        for (int e = 0; e < 8; e++)
            if (e != i1 && (i2 < 0 || lg[e] > lg[i2])) i2 = e;
        const float d = expf(lg[i2] - lg[i1]);     // <= 1
        const float w1 = 1.0f / (1.0f + d);
        const float w2 = d / (1.0f + d);
        g_idx[gw * 2 + 0] = i1; g_idx[gw * 2 + 1] = i2;
        g_w[gw * 2 + 0] = w1;  g_w[gw * 2 + 1] = w2;
        atomicAdd(&g_cnt[i1], 1);
        atomicAdd(&g_cnt[i2], 1);
    }
}

// ---------------- small helpers --------------------------------------------------------
__global__ void k_zero_cnt()
{
    const int i = threadIdx.x;
    if (i < Ee) { g_cnt[i] = 0; g_cur[i] = 0; }
}

__global__ void k_scan()
{
    if (threadIdx.x == 0) {
        int s = 0;
        for (int e = 0; e < Ee; e++) { g_off[e] = s; s += g_cnt[e]; }
    }
}

__global__ void k_place(int T)
{
    const int t = blockIdx.x * blockDim.x + threadIdx.x;
    if (t >= T) return;
    #pragma unroll
    for (int k = 0; k < 2; k++) {
        const int e = g_idx[t * 2 + k];
        const int p = atomicAdd(&g_cur[e], 1);
        g_list[g_off[e] + p] = t * 2 + k;
    }
}

// ---------------- K3: expert GEMM1  eh = silu(gather(x) @ ew1[e] + eb1[e]) -------------
__global__ void __launch_bounds__(256) k_gemm_exp1(const float* __restrict__ X,
                                                   const float* __restrict__ EW1,
                                                   const float* __restrict__ EB1)
{
    const int e = blockIdx.z;
    const int cnt = g_cnt[e];
    const int rowBase = blockIdx.x * 128;
    if (rowBase >= cnt) return;
    const int off = g_off[e];

    __shared__ float As[8][132];
    __shared__ float Bs[8][128];
    const int tid = threadIdx.x;
    const int colBase = blockIdx.y * 128;

    const int aRow = tid >> 1, aCol = (tid & 1) * 4;
    const int bRow = tid >> 5, bCol = (tid & 31) * 4;
    const int gRow = rowBase + aRow;
    const int lr = (gRow < cnt) ? gRow : (cnt - 1);
    const int packed = g_list[off + lr];
    const float* aPtr = X + (size_t)(packed >> 1) * Dd + aCol;
    const float* bPtr = EW1 + (size_t)e * Dd * Hh + (size_t)bRow * Hh + colBase + bCol;

    float acc[8][8];
    #pragma unroll
    for (int i = 0; i < 8; i++)
        #pragma unroll
        for (int j = 0; j < 8; j++) acc[i][j] = 0.0f;

    gemm_main(aPtr, bPtr, Hh, Dd, acc, As, Bs, tid);

    const int tx = tid & 15, ty = tid >> 4;
    const float* bias = EB1 + (size_t)e * Hh + colBase + tx * 8;
    #pragma unroll
    for (int i = 0; i < 8; i++) {
        const int r = rowBase + ty * 8 + i;
        if (r >= cnt) break;
        float* o = g_eh + (size_t)(off + r) * Hh + colBase + tx * 8;
        #pragma unroll
        for (int j = 0; j < 8; j++) {
            float c = acc[i][j] + bias[j];
            o[j] = silu_f(c);
        }
    }
}

// ---------------- K4: expert GEMM2  contrib = w * (eh @ ew2[e] + eb2[e]) ---------------
__global__ void __launch_bounds__(256) k_gemm_exp2(const float* __restrict__ EW2,
                                                   const float* __restrict__ EB2)
{
    const int e = blockIdx.z;
    const int cnt = g_cnt[e];
    const int rowBase = blockIdx.x * 128;
    if (rowBase >= cnt) return;
    const int off = g_off[e];

    __shared__ float As[8][132];
    __shared__ float Bs[8][128];
    const int tid = threadIdx.x;
    const int colBase = blockIdx.y * 128;

    const int aRow = tid >> 1, aCol = (tid & 1) * 4;
    const int bRow = tid >> 5, bCol = (tid & 31) * 4;
    const int gRow = rowBase + aRow;
    const int lr = (gRow < cnt) ? gRow : (cnt - 1);
    const float* aPtr = g_eh + (size_t)(off + lr) * Hh + aCol;
    const float* bPtr = EW2 + (size_t)e * Hh * Dd + (size_t)bRow * Dd + colBase + bCol;

    float acc[8][8];
    #pragma unroll
    for (int i = 0; i < 8; i++)
        #pragma unroll
        for (int j = 0; j < 8; j++) acc[i][j] = 0.0f;

    gemm_main(aPtr, bPtr, Dd, Hh, acc, As, Bs, tid);

    const int tx = tid & 15, ty = tid >> 4;
    const float* bias = EB2 + (size_t)e * Dd + colBase + tx * 8;
    #pragma unroll
    for (int i = 0; i < 8; i++) {
        const int r = rowBase + ty * 8 + i;
        if (r >= cnt) break;
        const int packed = g_list[off + r];
        const float wt = g_w[packed];
        float* o = g_contrib + (size_t)packed * Dd + colBase + tx * 8;
        #pragma unroll
        for (int j = 0; j < 8; j++)
            o[j] = wt * (acc[i][j] + bias[j]);
    }
}

// ---------------- K5: combine  out = x + contrib[2t] + contrib[2t+1] -------------------
__global__ void k_combine(const float* __restrict__ X, float* __restrict__ out, int T)
{
    const size_t i = ((size_t)blockIdx.x * blockDim.x + threadIdx.x) * 4;
    if (i >= (size_t)T * Dd) return;
    const size_t t = i / Dd;
    const size_t d = i % Dd;
    const float4 xv = *(const float4*)(X + i);
    const float4 c0 = *(const float4*)(g_contrib + (2 * t) * Dd + d);
    const float4 c1 = *(const float4*)(g_contrib + (2 * t + 1) * Dd + d);
    float4 o;
    o.x = xv.x + c0.x + c1.x;
    o.y = xv.y + c0.y + c1.y;
    o.z = xv.z + c0.z + c1.z;
    o.w = xv.w + c0.w + c1.w;
    *(float4*)(out + i) = o;
}

// ---------------- launch ----------------------------------------------------------------
extern "C" void kernel_launch(void* const* d_in, const int* in_sizes, int n_in,
                              void* d_out, int out_size)
{
    const float* x   = (const float*)d_in[0];
    const float* rw1 = (const float*)d_in[1];
    const float* rb1 = (const float*)d_in[2];
    const float* rw2 = (const float*)d_in[3];
    const float* rb2 = (const float*)d_in[4];
    const float* ew1 = (const float*)d_in[5];
    const float* eb1 = (const float*)d_in[6];
    const float* ew2 = (const float*)d_in[7];
    const float* eb2 = (const float*)d_in[8];
    float* out = (float*)d_out;

    const int T = in_sizes[0] / Dd;   // 8192 tokens

    k_zero_cnt<<<1, 32>>>();

    dim3 gR(Dd / 128, T / 128);                         // router GEMM1: 8 x 64
    k_gemm_router<<<gR, 256>>>(x, rw1, rb1);

    k_router2<<<(T * 32 + 255) / 256, 256>>>(rw2, rb2, T);
    k_scan<<<1, 1>>>();
    k_place<<<(T + 255) / 256, 256>>>(T);

    dim3 g1((2 * T + 127) / 128, Hh / 128, Ee);         // expert GEMM1
    k_gemm_exp1<<<g1, 256>>>(x, ew1, eb1);

    dim3 g2((2 * T + 127) / 128, Dd / 128, Ee);         // expert GEMM2
    k_gemm_exp2<<<g2, 256>>>(ew2, eb2);

    k_combine<<<(T * Dd / 4 + 255) / 256, 256>>>(x, out, T);
}